// round 9
// baseline (speedup 1.0000x reference)
#include <cuda_runtime.h>
#include <cstdint>
#include <math_constants.h>

#define BATCH   16384
#define S       2048
#define G       256
#define NT      256
#define EPT     (S / NT)   // 8
#define LISTCAP 32
#define RANKW   1793u      // S-G+1 ascending
#define RANKL   256u       // G ascending

// ---- order-preserving float<->uint transforms (fallback path only) ----
__device__ __forceinline__ uint32_t f2u(float f) {
    uint32_t b = __float_as_uint(f);
    return b ^ ((b & 0x80000000u) ? 0xFFFFFFFFu : 0x80000000u);
}
__device__ __forceinline__ float u2f(uint32_t u) {
    uint32_t b = (u & 0x80000000u) ? (u ^ 0x80000000u) : ~u;
    return __uint_as_float(b);
}

// monotone value->bin map, 4096 bins over [-4,4); 3 ops
__device__ __forceinline__ int val2kb(float s) {
    int i = __float2int_rd(fmaf(s, 512.0f, 2048.0f));
    return min(max(i, 0), 4095);
}

// ---- block exclusive scan (u32), 256 threads ----
__device__ __forceinline__ uint32_t block_exscan_u32(uint32_t v, uint32_t* st) {
    const uint32_t full = 0xffffffffu;
    int lane = threadIdx.x & 31, w = threadIdx.x >> 5;
    uint32_t inc = v;
#pragma unroll
    for (int o = 1; o < 32; o <<= 1) {
        uint32_t t = __shfl_up_sync(full, inc, o);
        if (lane >= o) inc += t;
    }
    if (lane == 31) st[w] = inc;
    __syncthreads();
    if (threadIdx.x < 32) {
        uint32_t t = (lane < 8) ? st[lane] : 0u;
        uint32_t it = t;
#pragma unroll
        for (int o = 1; o < 8; o <<= 1) {
            uint32_t x = __shfl_up_sync(full, it, o);
            if (lane >= o) it += x;
        }
        if (lane < 8) st[lane] = it - t;
    }
    __syncthreads();
    uint32_t r = (inc - v) + st[w];
    __syncthreads();
    return r;
}

// ---- block exclusive scan (packed u64, two independent u32 halves) ----
__device__ __forceinline__ unsigned long long block_exscan_u64(unsigned long long v,
                                                               unsigned long long* st) {
    const uint32_t full = 0xffffffffu;
    int lane = threadIdx.x & 31, w = threadIdx.x >> 5;
    unsigned long long inc = v;
#pragma unroll
    for (int o = 1; o < 32; o <<= 1) {
        unsigned long long t = __shfl_up_sync(full, inc, o);
        if (lane >= o) inc += t;
    }
    if (lane == 31) st[w] = inc;
    __syncthreads();
    if (threadIdx.x < 32) {
        unsigned long long t = (lane < 8) ? st[lane] : 0ull;
        unsigned long long it = t;
#pragma unroll
        for (int o = 1; o < 8; o <<= 1) {
            unsigned long long x = __shfl_up_sync(full, it, o);
            if (lane >= o) it += x;
        }
        if (lane < 8) st[lane] = it - t;
    }
    __syncthreads();
    unsigned long long r = (inc - v) + st[w];
    __syncthreads();
    return r;
}

// ---- rare fallback: exact key radix select (11/11/10 bits), one rank ----
__device__ uint32_t radix_one_f(const float* fr, uint32_t rank,
                                uint32_t* hist, uint32_t* st, uint32_t* pub) {
    const int tid = threadIdx.x;
    uint32_t pfx = 0, r = rank;
#pragma unroll
    for (int rnd = 0; rnd < 3; rnd++) {
        reinterpret_cast<uint4*>(hist)[tid] = make_uint4(0, 0, 0, 0);
        reinterpret_cast<uint4*>(hist)[NT + tid] = make_uint4(0, 0, 0, 0);
        __syncthreads();
#pragma unroll
        for (int k = 0; k < EPT; k++) {
            uint32_t u = f2u(fr[k]);
            bool ok; uint32_t bin;
            if (rnd == 0)      { ok = true;                bin = u >> 21; }
            else if (rnd == 1) { ok = (u >> 21) == pfx;    bin = (u >> 10) & 0x7FFu; }
            else               { ok = (u >> 10) == pfx;    bin = u & 0x3FFu; }
            if (ok) atomicAdd(&hist[bin], 1u);
        }
        __syncthreads();
        const int nb = (rnd == 2) ? 4 : 8;
        uint32_t c[8], sum = 0;
#pragma unroll
        for (int k = 0; k < 8; k++) {
            c[k] = (k < nb) ? hist[tid * nb + k] : 0u;
            sum += c[k];
        }
        uint32_t exc = block_exscan_u32(sum, st);
        if (exc < r && r <= exc + sum) {
            uint32_t run = exc;
#pragma unroll
            for (int k = 0; k < 8; k++) {
                if (k < nb && r > run && r <= run + c[k]) {
                    pub[18] = tid * nb + k; pub[19] = r - run;
                }
                run += c[k];
            }
        }
        __syncthreads();
        uint32_t bin = pub[18]; r = pub[19];
        __syncthreads();
        pfx = (rnd == 2) ? ((pfx << 10) | bin) : ((pfx << 11) | bin);
    }
    return pfx;
}

__global__ __launch_bounds__(NT, 6)
void portfolio_kernel(const float* __restrict__ scores,
                      const float* __restrict__ short_ratio,
                      float* __restrict__ out) {
    const int row = blockIdx.x;
    const int tid = threadIdx.x;
    const int lane = tid & 31;
    const int wid = tid >> 5;
    const uint32_t full = 0xffffffffu;

    __shared__ __align__(16) uint32_t hist[2048];   // fine: hA=[0,256) hB=[256,512); fallback radix: all
    __shared__ uint32_t st32[8];
    __shared__ unsigned long long st64[8];
    __shared__ unsigned long long w4[8][4];
    __shared__ float wmaxs[8], wmins[8];
    __shared__ uint32_t pub[20];
    __shared__ uint32_t pub2[8];
    __shared__ uint32_t cnt2[2];
    __shared__ float listW[LISTCAP], listL[LISTCAP];
    __shared__ float sredf[16];
    __shared__ unsigned long long sredu[8];

    uint32_t* const hA = hist;
    uint32_t* const hB = hist + 256;

    // ---- load row, compute packed kb, coarse nibble counts, local min/max ----
    const float4* rowp = reinterpret_cast<const float4*>(scores + (size_t)row * S);
    float fr[8];
    uint32_t kbp[4];   // 8 x 16-bit kb values
    unsigned long long cnt = 0ull;
    float lmax = -CUDART_INF_F, lmin = CUDART_INF_F;
#pragma unroll
    for (int k = 0; k < 2; k++) {
        float4 v = rowp[tid + k * NT];
        float s0 = v.x, s1 = v.y, s2 = v.z, s3 = v.w;
        fr[k * 4 + 0] = s0; fr[k * 4 + 1] = s1; fr[k * 4 + 2] = s2; fr[k * 4 + 3] = s3;
        int i0 = val2kb(s0), i1 = val2kb(s1), i2 = val2kb(s2), i3 = val2kb(s3);
        kbp[k * 2 + 0] = (uint32_t)i0 | ((uint32_t)i1 << 16);
        kbp[k * 2 + 1] = (uint32_t)i2 | ((uint32_t)i3 << 16);
        cnt += 1ull << ((i0 >> 8) * 4);
        cnt += 1ull << ((i1 >> 8) * 4);
        cnt += 1ull << ((i2 >> 8) * 4);
        cnt += 1ull << ((i3 >> 8) * 4);
        lmax = fmaxf(lmax, fmaxf(fmaxf(s0, s1), fmaxf(s2, s3)));
        lmin = fminf(lmin, fminf(fminf(s0, s1), fminf(s2, s3)));
    }
    hA[tid] = 0;
    hB[tid] = 0;
    if (tid < 2) cnt2[tid] = 0;
#pragma unroll
    for (int o = 16; o; o >>= 1) {
        lmax = fmaxf(lmax, __shfl_xor_sync(full, lmax, o));
        lmin = fminf(lmin, __shfl_xor_sync(full, lmin, o));
    }
    if (lane == 0) { wmaxs[wid] = lmax; wmins[wid] = lmin; }

    // ---- coarse pass: register nibble histogram -> per-warp 16-bit lanes ----
    unsigned long long be = cnt & 0x0F0F0F0F0F0F0F0Full;          // digits 0,2,..,14
    unsigned long long bo = (cnt >> 4) & 0x0F0F0F0F0F0F0F0Full;   // digits 1,3,..,15
#pragma unroll
    for (int o = 1; o <= 8; o <<= 1) {   // byte lanes, max 128 < 256
        be += __shfl_xor_sync(full, be, o);
        bo += __shfl_xor_sync(full, bo, o);
    }
    {
        const unsigned long long m16 = 0x00FF00FF00FF00FFull;
        unsigned long long q0 = be & m16;           // digits 0,4,8,12
        unsigned long long q1 = (be >> 8) & m16;    // digits 2,6,10,14
        unsigned long long q2 = bo & m16;           // digits 1,5,9,13
        unsigned long long q3 = (bo >> 8) & m16;    // digits 3,7,11,15
        q0 += __shfl_xor_sync(full, q0, 16);
        q1 += __shfl_xor_sync(full, q1, 16);
        q2 += __shfl_xor_sync(full, q2, 16);
        q3 += __shfl_xor_sync(full, q3, 16);
        if (lane == 0) {
            w4[wid][0] = q0; w4[wid][1] = q1; w4[wid][2] = q2; w4[wid][3] = q3;
        }
    }
    __syncthreads();

    // ---- thread 0: decode coarse histogram, locate both coarse bins ----
    if (tid == 0) {
        unsigned long long t0 = 0, t1 = 0, t2 = 0, t3 = 0;
        float gmax = -CUDART_INF_F, gmin = CUDART_INF_F;
#pragma unroll
        for (int w = 0; w < 8; w++) {
            t0 += w4[w][0]; t1 += w4[w][1]; t2 += w4[w][2]; t3 += w4[w][3];
            gmax = fmaxf(gmax, wmaxs[w]); gmin = fminf(gmin, wmins[w]);
        }
        uint32_t run = 0, cw = 0, cl = 0, cpw = 0, cpl = 0;
#pragma unroll
        for (int d = 0; d < 16; d++) {
            int idx = ((d & 1) << 1) | ((d >> 1) & 1);
            unsigned long long src = (idx == 0) ? t0 : (idx == 1) ? t1 : (idx == 2) ? t2 : t3;
            uint32_t c = (uint32_t)((src >> (16 * (d >> 2))) & 0xFFFFull);
            if (RANKW > run && RANKW <= run + c) { cw = (uint32_t)d; cpw = run; }
            if (RANKL > run && RANKL <= run + c) { cl = (uint32_t)d; cpl = run; }
            run += c;
        }
        pub[0] = cw;                 // coarse bin W
        pub[1] = RANKW - cpw;        // rank within coarse bin W
        pub[2] = cpw;                // coarse prefix W (elements in bins < cw)
        pub[3] = cl;
        pub[4] = RANKL - cpl;
        pub[5] = cpl;
        pub[6] = __float_as_uint(gmax);
        pub[7] = __float_as_uint(gmin);
        pub[8] = (cw == cl) ? 1u : 0u;   // degenerate -> fallback
    }
    __syncthreads();
    const uint32_t cW16 = pub[0]; const uint32_t rWc = pub[1]; const uint32_t CPw = pub[2];
    const uint32_t cL16 = pub[3]; const uint32_t rLc = pub[4]; const uint32_t CPl = pub[5];
    const float maxF = __uint_as_float(pub[6]);
    const float minF = __uint_as_float(pub[7]);
    const bool flag16 = (pub[8] != 0u);

    uint32_t fW = 0, FPw = 0, FCw = 0, rWf = 0;
    uint32_t fL = 0, FPl = 0, FCl = 0, rLf = 0;

    if (!flag16) {
        // ---- fine pass: sparse atomics only into the two crossing coarse bins ----
#pragma unroll
        for (int k = 0; k < EPT; k++) {
            uint32_t kb = (kbp[k >> 1] >> (16 * (k & 1))) & 0xFFFFu;
            uint32_t hi = kb >> 8;
            if (hi == cW16) atomicAdd(&hA[kb & 0xFFu], 1u);
            if (hi == cL16) atomicAdd(&hB[kb & 0xFFu], 1u);
        }
        __syncthreads();
        // ---- one packed scan over both fine histograms (1 bin per thread) ----
        {
            uint32_t sa = hA[tid], sb = hB[tid];
            unsigned long long e =
                block_exscan_u64((unsigned long long)sa | ((unsigned long long)sb << 32), st64);
            uint32_t ea = (uint32_t)e, eb = (uint32_t)(e >> 32);
            if (ea < rWc && rWc <= ea + sa) {
                pub[9] = (uint32_t)tid; pub[10] = ea; pub[11] = sa; pub[12] = rWc - ea;
            }
            if (eb < rLc && rLc <= eb + sb) {
                pub[13] = (uint32_t)tid; pub[14] = eb; pub[15] = sb; pub[16] = rLc - eb;
            }
            __syncthreads();
        }
        fW = pub[9];  FPw = pub[10]; FCw = pub[11]; rWf = pub[12];
        fL = pub[13]; FPl = pub[14]; FCl = pub[15]; rLf = pub[16];
    }

    const bool fastsel = !flag16 && (FCw <= LISTCAP) && (FCl <= LISTCAP);
    float swv, slv, sW, sL;
    int nWgt, nWeq, nLlt, nLeq;

    if (fastsel) {
        const uint32_t keyW = (cW16 << 8) | fW;
        const uint32_t keyL = (cL16 << 8) | fL;
        // ---- fused capture + coarse exp-sums (bin-level classification) ----
        float sWc = 0.0f, sLc = 0.0f;
#pragma unroll
        for (int k = 0; k < EPT; k++) {
            uint32_t kb = (kbp[k >> 1] >> (16 * (k & 1))) & 0xFFFFu;
            float s = fr[k];
            if (kb == keyW) {
                uint32_t i = atomicAdd(&cnt2[0], 1u);
                listW[i] = s;
            }
            if (kb == keyL) {
                uint32_t i = atomicAdd(&cnt2[1], 1u);
                listL[i] = s;
            }
            bool gtB = (kb > keyW), ltB = (kb < keyL);
            float ex = __expf(gtB ? (s - maxF) : (minF - s));
            sWc += gtB ? ex : 0.0f;
            sLc += ltB ? ex : 0.0f;
        }
#pragma unroll
        for (int o = 16; o; o >>= 1) {
            sWc += __shfl_xor_sync(full, sWc, o);
            sLc += __shfl_xor_sync(full, sLc, o);
        }
        if (lane == 0) { sredf[wid] = sWc; sredf[8 + wid] = sLc; }
        __syncthreads();

        // ---- warps 0/1: sort candidates + ballots; warp 2: finalize coarse sums ----
        if (wid < 2) {
            const uint32_t n = (wid == 0) ? FCw : FCl;
            float v = ((uint32_t)lane < n) ? (wid == 0 ? listW[lane] : listL[lane])
                                           : CUDART_INF_F;
#pragma unroll
            for (int k = 2; k <= 32; k <<= 1) {
#pragma unroll
                for (int j = k >> 1; j > 0; j >>= 1) {
                    float o = __shfl_xor_sync(full, v, j);
                    bool up = ((lane & k) == 0);
                    bool lower = ((lane & j) == 0);
                    float mn = fminf(v, o), mx = fmaxf(v, o);
                    v = (lower == up) ? mn : mx;
                }
            }
            uint32_t rank = (wid == 0) ? rWf : rLf;   // 1-based
            float sel = __shfl_sync(full, v, (int)(rank - 1));
            bool valid = ((uint32_t)lane < n);
            if (wid == 0) {
                uint32_t mgt = __ballot_sync(full, valid && v > sel);
                uint32_t meq = __ballot_sync(full, valid && v == sel);
                float cs = (valid && v > sel) ? __expf(v - maxF) : 0.0f;
#pragma unroll
                for (int o = 16; o; o >>= 1) cs += __shfl_xor_sync(full, cs, o);
                if (lane == 0) {
                    pub2[0] = __float_as_uint(sel);
                    pub2[1] = __popc(mgt);
                    pub2[2] = __popc(meq);
                    pub2[3] = __float_as_uint(cs);
                }
            } else {
                uint32_t mlt = __ballot_sync(full, valid && v < sel);
                uint32_t meq = __ballot_sync(full, valid && v == sel);
                float cs = (valid && v < sel) ? __expf(minF - v) : 0.0f;
#pragma unroll
                for (int o = 16; o; o >>= 1) cs += __shfl_xor_sync(full, cs, o);
                if (lane == 0) {
                    pub2[4] = __float_as_uint(sel);
                    pub2[5] = __popc(mlt);
                    pub2[6] = __popc(meq);
                    pub2[7] = __float_as_uint(cs);
                }
            }
        } else if (wid == 2) {
            float a = (lane < 8) ? sredf[lane] : 0.0f;
            float b = (lane < 8) ? sredf[8 + lane] : 0.0f;
#pragma unroll
            for (int o = 4; o; o >>= 1) {
                a += __shfl_xor_sync(full, a, o);
                b += __shfl_xor_sync(full, b, o);
            }
            if (lane == 0) { sredf[0] = a; sredf[8] = b; }
        }
        __syncthreads();

        swv = __uint_as_float(pub2[0]);
        slv = __uint_as_float(pub2[4]);
        nWgt = (int)(S - CPw - FPw - FCw) + (int)pub2[1];
        nWeq = (int)pub2[2];
        sW = sredf[0] + __uint_as_float(pub2[3]);
        nLlt = (int)(CPl + FPl) + (int)pub2[5];
        nLeq = (int)pub2[6];
        sL = sredf[8] + __uint_as_float(pub2[7]);
    } else {
        // ---- RARE fallback: exact full-key radix select + full count pass ----
        uint32_t kW = radix_one_f(fr, RANKW, hist, st32, pub);
        uint32_t kL = radix_one_f(fr, RANKL, hist, st32, pub);
        swv = u2f(kW);
        slv = u2f(kL);
        unsigned long long packed = 0ull;
        float a2 = 0.0f, b2 = 0.0f;
#pragma unroll
        for (int k = 0; k < EPT; k++) {
            float s = fr[k];
            bool gtW = (s > swv), eqW = (s == swv), ltL = (s < slv), eqL = (s == slv);
            float ex = __expf(gtW ? (s - maxF) : (minF - s));
            a2 += gtW ? ex : 0.0f;
            b2 += ltL ? ex : 0.0f;
            packed += (unsigned long long)gtW
                    + ((unsigned long long)eqW << 16)
                    + ((unsigned long long)ltL << 32)
                    + ((unsigned long long)eqL << 48);
        }
#pragma unroll
        for (int o = 16; o; o >>= 1) {
            packed += __shfl_xor_sync(full, packed, o);
            a2 += __shfl_xor_sync(full, a2, o);
            b2 += __shfl_xor_sync(full, b2, o);
        }
        if (lane == 0) { sredu[wid] = packed; sredf[wid] = a2; sredf[8 + wid] = b2; }
        __syncthreads();
        if (tid < 32) {
            unsigned long long c = (lane < 8) ? sredu[lane] : 0ull;
            float a = (lane < 8) ? sredf[lane] : 0.0f;
            float b = (lane < 8) ? sredf[8 + lane] : 0.0f;
#pragma unroll
            for (int o = 4; o; o >>= 1) {
                c += __shfl_xor_sync(full, c, o);
                a += __shfl_xor_sync(full, a, o);
                b += __shfl_xor_sync(full, b, o);
            }
            if (lane == 0) { sredu[0] = c; sredf[0] = a; sredf[8] = b; }
        }
        __syncthreads();
        packed = sredu[0];
        sW = sredf[0];
        sL = sredf[8];
        nWgt = (int)(packed & 0xFFFFu);
        nWeq = (int)((packed >> 16) & 0xFFFFu);
        nLlt = (int)((packed >> 32) & 0xFFFFu);
        nLeq = (int)((packed >> 48) & 0xFFFFu);
    }

    const int eWc = G - nWgt;
    const int eLc = G - nLlt;
    const float expWeq = __expf(swv - maxF);
    const float expLeq = __expf(minF - slv);
    const float invW = 1.0f / (sW + (float)eWc * expWeq);
    const float invL = 1.0f / (sL + (float)eLc * expLeq);
    const float wEq = expWeq * invW;
    const float lEq = expLeq * invL;

    float4* outL = reinterpret_cast<float4*>(out + (size_t)row * S);
    float4* outSh = reinterpret_cast<float4*>(out + (size_t)BATCH * S + (size_t)row * S);
    const bool noTie = (nWeq == eWc) && (nLeq == eLc);

    if (noTie) {
        // ---- write: one expf per element, branch-free selects ----
#pragma unroll
        for (int k = 0; k < 2; k++) {
            float lw[4], sw4[4];
#pragma unroll
            for (int c = 0; c < 4; c++) {
                float s = fr[k * 4 + c];
                bool gtW = (s > swv), ltL = (s < slv);
                float ex = __expf(gtW ? (s - maxF) : (minF - s));
                lw[c]  = gtW ? ex * invW : ((s == swv) ? wEq : 0.0f);
                sw4[c] = ltL ? ex * invL : ((s == slv) ? lEq : 0.0f);
            }
            outL[tid + k * NT]  = make_float4(lw[0], lw[1], lw[2], lw[3]);
            outSh[tid + k * NT] = make_float4(sw4[0], sw4[1], sw4[2], sw4[3]);
        }
    } else {
        // ---- RARE tie path: rank equals by global index (k, tid, c) via exscan ----
        uint32_t qW0 = 0, qW1 = 0, qL0 = 0, qL1 = 0;
#pragma unroll
        for (int c = 0; c < 4; c++) {
            qW0 += (fr[c] == swv);       qL0 += (fr[c] == slv);
            qW1 += (fr[4 + c] == swv);   qL1 += (fr[4 + c] == slv);
        }
        unsigned long long pk = (unsigned long long)qW0 | ((unsigned long long)qW1 << 16) |
                                ((unsigned long long)qL0 << 32) | ((unsigned long long)qL1 << 48);
        unsigned long long ex = block_exscan_u64(pk, st64);
        if (tid == NT - 1) sredu[7] = ex + pk;
        __syncthreads();
        unsigned long long tot = sredu[7];
        const uint32_t totW0 = (uint32_t)(tot & 0xFFFFull);
        const uint32_t totL0 = (uint32_t)((tot >> 32) & 0xFFFFull);
#pragma unroll
        for (int k = 0; k < 2; k++) {
            uint32_t beforeW = k ? totW0 + (uint32_t)((ex >> 16) & 0xFFFFull)
                                 : (uint32_t)(ex & 0xFFFFull);
            uint32_t beforeL = k ? totL0 + (uint32_t)((ex >> 48) & 0xFFFFull)
                                 : (uint32_t)((ex >> 32) & 0xFFFFull);
            float lw[4], sw4[4];
#pragma unroll
            for (int c = 0; c < 4; c++) {
                float s = fr[k * 4 + c];
                float lval = 0.0f, sval = 0.0f;
                if (s > swv) lval = __expf(s - maxF) * invW;
                else if (s == swv) { lval = (beforeW < (uint32_t)eWc) ? wEq : 0.0f; beforeW++; }
                if (s < slv) sval = __expf(minF - s) * invL;
                else if (s == slv) { sval = (beforeL < (uint32_t)eLc) ? lEq : 0.0f; beforeL++; }
                lw[c] = lval;
                sw4[c] = sval;
            }
            outL[tid + k * NT]  = make_float4(lw[0], lw[1], lw[2], lw[3]);
            outSh[tid + k * NT] = make_float4(sw4[0], sw4[1], sw4[2], sw4[3]);
        }
    }

    // ---- short_ratio passthrough (clipped) ----
    if (tid == 0) {
        float r = short_ratio[row];
        r = fminf(fmaxf(r, 0.0f), 1.0f);
        out[(size_t)2 * BATCH * S + row] = r;
    }
}

extern "C" void kernel_launch(void* const* d_in, const int* in_sizes, int n_in,
                              void* d_out, int out_size) {
    const float* scores = (const float*)d_in[0];
    const float* ratio  = (const float*)d_in[1];
    if (n_in >= 2 && in_sizes[0] == BATCH && in_sizes[1] == BATCH * S) {
        const float* t = scores; scores = ratio; ratio = t;
    }
    portfolio_kernel<<<BATCH, NT>>>(scores, ratio, (float*)d_out);
}